// round 4
// baseline (speedup 1.0000x reference)
#include <cuda_runtime.h>
#include <cuda_bf16.h>

// ZBL screened nuclear repulsion:
//   expv = Dij/d * (Zi^p + Zj^p)
//   vij  = sum_k c[k] * exp(-a[k]*expv)
//   out  = segment_sum(vij, idx_i)   (idx_i sorted)
//
// Inputs (metadata order):
//   0: Z     int32  [500000]
//   1: Dij   f32    [16000000]
//   2: idx_i int32  [16000000]   (sorted)
//   3: idx_j int32  [16000000]
//   4: p     f32    [1]
//   5: d     f32    [1]
//   6: c     f32    [4]
//   7: a     f32    [4]
// Output: f32 [500000]
//
// R4 design: per-atom zpa[] = Z^p table precomputed once (removes the
// LDG->LDS 2-level chain and all shared-mem bank conflicts from the hot
// l1tex pipe, which R3 ncu showed as the binder at 75.8%). EPT=8 with
// front-batched vector loads; streaming loads use .cs to keep L1 for the
// random gather table.

#define MAX_ATOMS 500000
#define EPT       8
#define TPB       256

__device__ float g_zpa[MAX_ATOMS];  // zpa[atom] = Z[atom]^p
__device__ float g_params[12];      // [0]=1/d, [1..4]=c, [5..8]=b_k=-a_k*log2(e)

// ---------------------------------------------------------------------------
// Init kernel: zero poisoned output, build per-atom z^p table + params.
// ---------------------------------------------------------------------------
__global__ void zbl_init_kernel(const int*   __restrict__ Z,
                                const float* __restrict__ p_ptr,
                                const float* __restrict__ d_ptr,
                                const float* __restrict__ c_ptr,
                                const float* __restrict__ a_ptr,
                                float* __restrict__ out, int n_out)
{
    const int t = blockIdx.x * blockDim.x + threadIdx.x;
    const float p = *p_ptr;
    if (t < n_out) {
        out[t] = 0.0f;
        // z^p = 2^(p*log2 z); z=0 -> log2=-inf -> 2^-inf = 0 = pow(0,p). OK.
        g_zpa[t] = exp2f(p * log2f((float)Z[t]));
    }
    if (t == 0) {
        const float L2E = 1.4426950408889634f;
        g_params[0] = 1.0f / (*d_ptr);
        #pragma unroll
        for (int k = 0; k < 4; k++) {
            g_params[1 + k] = c_ptr[k];
            g_params[5 + k] = -a_ptr[k] * L2E;
        }
    }
}

__device__ __forceinline__ float ex2(float x) {
    float y;
    asm("ex2.approx.f32 %0, %1;" : "=f"(y) : "f"(x));
    return y;
}

// ---------------------------------------------------------------------------
// Main kernel: 8 edges/thread, front-batched vector loads, single-level
// float gathers, per-thread run merge + warp-segmented scan, boundary
// atomics only.
// ---------------------------------------------------------------------------
__global__ __launch_bounds__(TPB)
void zbl_main_kernel(const float* __restrict__ Dij,
                     const int*   __restrict__ idx_i,
                     const int*   __restrict__ idx_j,
                     float*       __restrict__ out,
                     int E)
{
    const float invd = __ldg(&g_params[0]);
    const float c0 = __ldg(&g_params[1]), c1 = __ldg(&g_params[2]);
    const float c2 = __ldg(&g_params[3]), c3 = __ldg(&g_params[4]);
    const float b0 = __ldg(&g_params[5]), b1 = __ldg(&g_params[6]);
    const float b2 = __ldg(&g_params[7]), b3 = __ldg(&g_params[8]);

    const int tid  = blockIdx.x * blockDim.x + threadIdx.x;
    const int base = tid * EPT;

    int   cur = -1;     // pending segment id (tail)
    float acc = 0.0f;   // pending segment sum

    if (base + EPT <= E) {
        // ---- front-batched streaming loads (evict-first: keep L1 for zpa) ----
        const float4 da = __ldcs(reinterpret_cast<const float4*>(Dij)   + 2*tid);
        const float4 db = __ldcs(reinterpret_cast<const float4*>(Dij)   + 2*tid + 1);
        const int4   ia = __ldcs(reinterpret_cast<const int4*>(idx_i)   + 2*tid);
        const int4   ib = __ldcs(reinterpret_cast<const int4*>(idx_i)   + 2*tid + 1);
        const int4   ja = __ldcs(reinterpret_cast<const int4*>(idx_j)   + 2*tid);
        const int4   jb = __ldcs(reinterpret_cast<const int4*>(idx_j)   + 2*tid + 1);

        // ---- single-level float gathers (all independent -> max MLP) ----
        const float fi0 = __ldg(g_zpa + ia.x), fi1 = __ldg(g_zpa + ia.y);
        const float fi2 = __ldg(g_zpa + ia.z), fi3 = __ldg(g_zpa + ia.w);
        const float fi4 = __ldg(g_zpa + ib.x), fi5 = __ldg(g_zpa + ib.y);
        const float fi6 = __ldg(g_zpa + ib.z), fi7 = __ldg(g_zpa + ib.w);
        const float fj0 = __ldg(g_zpa + ja.x), fj1 = __ldg(g_zpa + ja.y);
        const float fj2 = __ldg(g_zpa + ja.z), fj3 = __ldg(g_zpa + ja.w);
        const float fj4 = __ldg(g_zpa + jb.x), fj5 = __ldg(g_zpa + jb.y);
        const float fj6 = __ldg(g_zpa + jb.z), fj7 = __ldg(g_zpa + jb.w);

        const float e0 = da.x * invd * (fi0 + fj0);
        const float e1 = da.y * invd * (fi1 + fj1);
        const float e2 = da.z * invd * (fi2 + fj2);
        const float e3 = da.w * invd * (fi3 + fj3);
        const float e4 = db.x * invd * (fi4 + fj4);
        const float e5 = db.y * invd * (fi5 + fj5);
        const float e6 = db.z * invd * (fi6 + fj6);
        const float e7 = db.w * invd * (fi7 + fj7);

        const float v0 = c0*ex2(b0*e0) + c1*ex2(b1*e0) + c2*ex2(b2*e0) + c3*ex2(b3*e0);
        const float v1 = c0*ex2(b0*e1) + c1*ex2(b1*e1) + c2*ex2(b2*e1) + c3*ex2(b3*e1);
        const float v2 = c0*ex2(b0*e2) + c1*ex2(b1*e2) + c2*ex2(b2*e2) + c3*ex2(b3*e2);
        const float v3 = c0*ex2(b0*e3) + c1*ex2(b1*e3) + c2*ex2(b2*e3) + c3*ex2(b3*e3);
        const float v4 = c0*ex2(b0*e4) + c1*ex2(b1*e4) + c2*ex2(b2*e4) + c3*ex2(b3*e4);
        const float v5 = c0*ex2(b0*e5) + c1*ex2(b1*e5) + c2*ex2(b2*e5) + c3*ex2(b3*e5);
        const float v6 = c0*ex2(b0*e6) + c1*ex2(b1*e6) + c2*ex2(b2*e6) + c3*ex2(b3*e6);
        const float v7 = c0*ex2(b0*e7) + c1*ex2(b1*e7) + c2*ex2(b2*e7) + c3*ex2(b3*e7);

        // ---- sequential merge of 8 sorted edges; flush interior runs ----
        cur = ia.x; acc = v0;
        if (ia.y == cur) acc += v1; else { atomicAdd(out + cur, acc); cur = ia.y; acc = v1; }
        if (ia.z == cur) acc += v2; else { atomicAdd(out + cur, acc); cur = ia.z; acc = v2; }
        if (ia.w == cur) acc += v3; else { atomicAdd(out + cur, acc); cur = ia.w; acc = v3; }
        if (ib.x == cur) acc += v4; else { atomicAdd(out + cur, acc); cur = ib.x; acc = v4; }
        if (ib.y == cur) acc += v5; else { atomicAdd(out + cur, acc); cur = ib.y; acc = v5; }
        if (ib.z == cur) acc += v6; else { atomicAdd(out + cur, acc); cur = ib.z; acc = v6; }
        if (ib.w == cur) acc += v7; else { atomicAdd(out + cur, acc); cur = ib.w; acc = v7; }
    } else if (base < E) {
        // ---- remainder path: scalar, direct atomics ----
        for (int e = base; e < E; e++) {
            const int   si = __ldg(idx_i + e);
            const int   sj = __ldg(idx_j + e);
            const float ev = __ldg(Dij + e) * invd * (__ldg(g_zpa + si) + __ldg(g_zpa + sj));
            const float v  = c0*ex2(b0*ev) + c1*ex2(b1*ev) + c2*ex2(b2*ev) + c3*ex2(b3*ev);
            atomicAdd(out + si, v);
        }
        cur = -1; acc = 0.0f;
    }

    // ---- warp-level segmented inclusive scan over the pending tails ----
    // idx_i sorted -> equal tail ids are contiguous across lanes; the last
    // lane of each run issues one atomicAdd. Idle lanes carry cur=-1 which
    // never matches a valid id and is guarded below.
    const unsigned m = 0xFFFFFFFFu;
    const int lane = threadIdx.x & 31;
    #pragma unroll
    for (int o = 1; o < 32; o <<= 1) {
        const float vv = __shfl_up_sync(m, acc, o);
        const int   ss = __shfl_up_sync(m, cur, o);
        if (lane >= o && ss == cur) acc += vv;
    }
    const int nxt = __shfl_down_sync(m, cur, 1);
    if (cur >= 0 && (lane == 31 || nxt != cur)) {
        atomicAdd(out + cur, acc);
    }
}

// ---------------------------------------------------------------------------
extern "C" void kernel_launch(void* const* d_in, const int* in_sizes, int n_in,
                              void* d_out, int out_size)
{
    const int*   Z     = (const int*)  d_in[0];
    const float* Dij   = (const float*)d_in[1];
    const int*   idx_i = (const int*)  d_in[2];
    const int*   idx_j = (const int*)  d_in[3];
    const float* p_ptr = (const float*)d_in[4];
    const float* d_ptr = (const float*)d_in[5];
    const float* c_ptr = (const float*)d_in[6];
    const float* a_ptr = (const float*)d_in[7];
    float* out = (float*)d_out;

    const int E = in_sizes[1];
    const int N = out_size;

    // 1) zero output + build per-atom z^p table / params
    {
        const int blocks = (N + TPB - 1) / TPB;
        zbl_init_kernel<<<blocks, TPB>>>(Z, p_ptr, d_ptr, c_ptr, a_ptr, out, N);
    }

    // 2) fused edge compute + sorted segment reduction
    {
        const int threads = (E + EPT - 1) / EPT;
        const int blocks  = (threads + TPB - 1) / TPB;
        zbl_main_kernel<<<blocks, TPB>>>(Dij, idx_i, idx_j, out, E);
    }
}

// round 5
// speedup vs baseline: 1.0155x; 1.0155x over previous
#include <cuda_runtime.h>
#include <cuda_bf16.h>

// ZBL screened nuclear repulsion:
//   expv = Dij/d * (Zi^p + Zj^p)
//   vij  = sum_k c[k] * exp(-a[k]*expv)
//   out  = segment_sum(vij, idx_i)   (idx_i sorted)
//
// Inputs (metadata order):
//   0: Z     int32  [500000]
//   1: Dij   f32    [16000000]
//   2: idx_i int32  [16000000]   (sorted)
//   3: idx_j int32  [16000000]
//   4: p     f32    [1]
//   5: d     f32    [1]
//   6: c     f32    [4]
//   7: a     f32    [4]
// Output: f32 [500000]
//
// R5: exact R3 structure (EPT=4, __ldg, known-good l1tex-queue regime) with
// ONE change: gather precomputed zpa[atom] = Z[atom]^p / d directly instead
// of Z-gather + shared-table LDS. Removes the LDS bank-conflict traffic and
// the 2-level dependent chain from the binding l1tex pipe. R4 showed that
// EPT=8 front-batching overflows the 248-entry L1tex wavefront queue
// (MLP_p1 ~22 -> ~2x spread), so we stay at EPT=4.

#define MAX_ATOMS 500000
#define EPT       4
#define TPB       256

__device__ float g_zpa[MAX_ATOMS];  // zpa[atom] = Z[atom]^p / d
__device__ float g_params[8];       // [0..3]=c, [4..7]=b_k=-a_k*log2(e)

// ---------------------------------------------------------------------------
// Init kernel: zero poisoned output, build per-atom (z^p)/d table + params.
// ---------------------------------------------------------------------------
__global__ void zbl_init_kernel(const int*   __restrict__ Z,
                                const float* __restrict__ p_ptr,
                                const float* __restrict__ d_ptr,
                                const float* __restrict__ c_ptr,
                                const float* __restrict__ a_ptr,
                                float* __restrict__ out, int n_out)
{
    const int t = blockIdx.x * blockDim.x + threadIdx.x;
    if (t < n_out) {
        out[t] = 0.0f;
        const float p    = *p_ptr;
        const float invd = 1.0f / (*d_ptr);
        // z^p = exp2(p*log2 z); z=0 -> -inf -> 0, matching pow(0,p) for p>0.
        g_zpa[t] = exp2f(p * log2f((float)Z[t])) * invd;
    }
    if (t == 0) {
        const float L2E = 1.4426950408889634f;
        #pragma unroll
        for (int k = 0; k < 4; k++) {
            g_params[k]     = c_ptr[k];
            g_params[4 + k] = -a_ptr[k] * L2E;
        }
    }
}

__device__ __forceinline__ float ex2(float x) {
    float y;
    asm("ex2.approx.f32 %0, %1;" : "=f"(y) : "f"(x));
    return y;
}

// ---------------------------------------------------------------------------
// Main kernel: 4 edges/thread (R3's proven queue-friendly batching),
// single-level float gathers, per-thread run merge + warp-segmented scan,
// boundary atomics only.
// ---------------------------------------------------------------------------
__global__ __launch_bounds__(TPB)
void zbl_main_kernel(const float* __restrict__ Dij,
                     const int*   __restrict__ idx_i,
                     const int*   __restrict__ idx_j,
                     float*       __restrict__ out,
                     int E)
{
    const float c0 = __ldg(&g_params[0]), c1 = __ldg(&g_params[1]);
    const float c2 = __ldg(&g_params[2]), c3 = __ldg(&g_params[3]);
    const float b0 = __ldg(&g_params[4]), b1 = __ldg(&g_params[5]);
    const float b2 = __ldg(&g_params[6]), b3 = __ldg(&g_params[7]);

    const int tid  = blockIdx.x * blockDim.x + threadIdx.x;
    const int base = tid * EPT;

    int   cur = -1;     // pending segment id (tail)
    float acc = 0.0f;   // pending segment sum

    if (base + EPT <= E) {
        // ---- 3 streaming vector loads + 8 scalar gathers (MLP ~ R3) ----
        const float4 dd = __ldg(reinterpret_cast<const float4*>(Dij)   + tid);
        const int4   ii = __ldg(reinterpret_cast<const int4*>(idx_i)   + tid);
        const int4   jj = __ldg(reinterpret_cast<const int4*>(idx_j)   + tid);

        const float fi0 = __ldg(g_zpa + ii.x), fi1 = __ldg(g_zpa + ii.y);
        const float fi2 = __ldg(g_zpa + ii.z), fi3 = __ldg(g_zpa + ii.w);
        const float fj0 = __ldg(g_zpa + jj.x), fj1 = __ldg(g_zpa + jj.y);
        const float fj2 = __ldg(g_zpa + jj.z), fj3 = __ldg(g_zpa + jj.w);

        // invd is folded into the table, so expv = Dij * (zpi' + zpj')
        const float e0 = dd.x * (fi0 + fj0);
        const float e1 = dd.y * (fi1 + fj1);
        const float e2 = dd.z * (fi2 + fj2);
        const float e3 = dd.w * (fi3 + fj3);

        const float v0 = c0*ex2(b0*e0) + c1*ex2(b1*e0) + c2*ex2(b2*e0) + c3*ex2(b3*e0);
        const float v1 = c0*ex2(b0*e1) + c1*ex2(b1*e1) + c2*ex2(b2*e1) + c3*ex2(b3*e1);
        const float v2 = c0*ex2(b0*e2) + c1*ex2(b1*e2) + c2*ex2(b2*e2) + c3*ex2(b3*e2);
        const float v3 = c0*ex2(b0*e3) + c1*ex2(b1*e3) + c2*ex2(b2*e3) + c3*ex2(b3*e3);

        // ---- sequential merge of the 4 sorted edges; flush interior runs ----
        cur = ii.x; acc = v0;
        if (ii.y == cur) acc += v1; else { atomicAdd(out + cur, acc); cur = ii.y; acc = v1; }
        if (ii.z == cur) acc += v2; else { atomicAdd(out + cur, acc); cur = ii.z; acc = v2; }
        if (ii.w == cur) acc += v3; else { atomicAdd(out + cur, acc); cur = ii.w; acc = v3; }
    } else if (base < E) {
        // ---- remainder path: scalar, direct atomics ----
        for (int e = base; e < E; e++) {
            const int   si = __ldg(idx_i + e);
            const int   sj = __ldg(idx_j + e);
            const float ev = __ldg(Dij + e) * (__ldg(g_zpa + si) + __ldg(g_zpa + sj));
            const float v  = c0*ex2(b0*ev) + c1*ex2(b1*ev) + c2*ex2(b2*ev) + c3*ex2(b3*ev);
            atomicAdd(out + si, v);
        }
        cur = -1; acc = 0.0f;
    }

    // ---- warp-level segmented inclusive scan over the pending tails ----
    // idx_i sorted -> equal tail ids are contiguous across lanes; the last
    // lane of each run issues one atomicAdd.
    const unsigned m = 0xFFFFFFFFu;
    const int lane = threadIdx.x & 31;
    #pragma unroll
    for (int o = 1; o < 32; o <<= 1) {
        const float vv = __shfl_up_sync(m, acc, o);
        const int   ss = __shfl_up_sync(m, cur, o);
        if (lane >= o && ss == cur) acc += vv;
    }
    const int nxt = __shfl_down_sync(m, cur, 1);
    if (cur >= 0 && (lane == 31 || nxt != cur)) {
        atomicAdd(out + cur, acc);
    }
}

// ---------------------------------------------------------------------------
extern "C" void kernel_launch(void* const* d_in, const int* in_sizes, int n_in,
                              void* d_out, int out_size)
{
    const int*   Z     = (const int*)  d_in[0];
    const float* Dij   = (const float*)d_in[1];
    const int*   idx_i = (const int*)  d_in[2];
    const int*   idx_j = (const int*)  d_in[3];
    const float* p_ptr = (const float*)d_in[4];
    const float* d_ptr = (const float*)d_in[5];
    const float* c_ptr = (const float*)d_in[6];
    const float* a_ptr = (const float*)d_in[7];
    float* out = (float*)d_out;

    const int E = in_sizes[1];
    const int N = out_size;

    // 1) zero output + build per-atom (z^p)/d table / params
    {
        const int blocks = (N + TPB - 1) / TPB;
        zbl_init_kernel<<<blocks, TPB>>>(Z, p_ptr, d_ptr, c_ptr, a_ptr, out, N);
    }

    // 2) fused edge compute + sorted segment reduction
    {
        const int threads = (E + EPT - 1) / EPT;
        const int blocks  = (threads + TPB - 1) / TPB;
        zbl_main_kernel<<<blocks, TPB>>>(Dij, idx_i, idx_j, out, E);
    }
}

// round 6
// speedup vs baseline: 1.5960x; 1.5716x over previous
#include <cuda_runtime.h>
#include <cuda_bf16.h>

// ZBL screened nuclear repulsion:
//   expv = Dij/d * (Zi^p + Zj^p)
//   vij  = sum_k c[k] * exp(-a[k]*expv)
//   out  = segment_sum(vij, idx_i)   (idx_i sorted)
//
// Inputs (metadata order):
//   0: Z     int32  [500000]
//   1: Dij   f32    [16000000]
//   2: idx_i int32  [16000000]   (sorted)
//   3: idx_j int32  [16000000]
//   4: p     f32    [1]
//   5: d     f32    [1]
//   6: c     f32    [4]
//   7: a     f32    [4]
// Output: f32 [500000]
//
// R6: proven R3 skeleton (EPT=4, gather the INPUT Z array — the per-atom
// __device__ float-table variants of R4/R5 regressed 1.5x twice). The zp
// lookup moves off the binding l1tex pipe onto MUFU:
//   z^p = ex2(p * lg2(z))   (2 MUFU + 1 I2F, replaces LDS with ~3-way
//   random bank conflicts). 1/d is folded into the b_k coefficients.
// Output zeroing is a cudaMemsetAsync graph node (no init kernel at all).

#define EPT  4
#define TPB  256

__device__ __forceinline__ float ex2(float x) {
    float y;
    asm("ex2.approx.f32 %0, %1;" : "=f"(y) : "f"(x));
    return y;
}
__device__ __forceinline__ float lg2(float x) {
    float y;
    asm("lg2.approx.f32 %0, %1;" : "=f"(y) : "f"(x));
    return y;
}

// ---------------------------------------------------------------------------
// Main kernel: 4 edges/thread, vector streaming loads, Z gathers from the
// input array, MUFU-computed z^p, per-thread run merge + warp-segmented
// scan, boundary atomics only.
// ---------------------------------------------------------------------------
__global__ __launch_bounds__(TPB)
void zbl_main_kernel(const float* __restrict__ Dij,
                     const int*   __restrict__ idx_i,
                     const int*   __restrict__ idx_j,
                     const int*   __restrict__ Z,
                     const float* __restrict__ p_ptr,
                     const float* __restrict__ d_ptr,
                     const float* __restrict__ c_ptr,
                     const float* __restrict__ a_ptr,
                     float*       __restrict__ out,
                     int E)
{
    // Uniform scalar parameter loads (broadcast; L1-hit after first warp).
    const float p    = __ldg(p_ptr);
    const float invd = 1.0f / __ldg(d_ptr);
    const float c0 = __ldg(c_ptr + 0), c1 = __ldg(c_ptr + 1);
    const float c2 = __ldg(c_ptr + 2), c3 = __ldg(c_ptr + 3);
    // b_k = -a_k * log2(e) / d   (folds both the exp->ex2 change of base
    // and the 1/d of expv into one coefficient)
    const float NL2E = -1.4426950408889634f * invd;
    const float b0 = __ldg(a_ptr + 0) * NL2E, b1 = __ldg(a_ptr + 1) * NL2E;
    const float b2 = __ldg(a_ptr + 2) * NL2E, b3 = __ldg(a_ptr + 3) * NL2E;

    const int tid  = blockIdx.x * blockDim.x + threadIdx.x;
    const int base = tid * EPT;

    int   cur = -1;     // pending segment id (tail)
    float acc = 0.0f;   // pending segment sum

    if (base + EPT <= E) {
        // ---- 3 streaming vector loads + 8 scalar gathers (R3's proven mix) ----
        const float4 dd = __ldg(reinterpret_cast<const float4*>(Dij)   + tid);
        const int4   ii = __ldg(reinterpret_cast<const int4*>(idx_i)   + tid);
        const int4   jj = __ldg(reinterpret_cast<const int4*>(idx_j)   + tid);

        const int zi0 = __ldg(Z + ii.x), zi1 = __ldg(Z + ii.y);
        const int zi2 = __ldg(Z + ii.z), zi3 = __ldg(Z + ii.w);
        const int zj0 = __ldg(Z + jj.x), zj1 = __ldg(Z + jj.y);
        const int zj2 = __ldg(Z + jj.z), zj3 = __ldg(Z + jj.w);

        // ---- z^p via MUFU: ex2(p*lg2(z)); z=0 -> lg2=-inf -> ex2=0 = pow(0,p) ----
        const float fi0 = ex2(p * lg2((float)zi0));
        const float fi1 = ex2(p * lg2((float)zi1));
        const float fi2 = ex2(p * lg2((float)zi2));
        const float fi3 = ex2(p * lg2((float)zi3));
        const float fj0 = ex2(p * lg2((float)zj0));
        const float fj1 = ex2(p * lg2((float)zj1));
        const float fj2 = ex2(p * lg2((float)zj2));
        const float fj3 = ex2(p * lg2((float)zj3));

        // expv*(-a_k*log2e) is produced by b_k which already carries 1/d
        const float e0 = dd.x * (fi0 + fj0);
        const float e1 = dd.y * (fi1 + fj1);
        const float e2 = dd.z * (fi2 + fj2);
        const float e3 = dd.w * (fi3 + fj3);

        const float v0 = c0*ex2(b0*e0) + c1*ex2(b1*e0) + c2*ex2(b2*e0) + c3*ex2(b3*e0);
        const float v1 = c0*ex2(b0*e1) + c1*ex2(b1*e1) + c2*ex2(b2*e1) + c3*ex2(b3*e1);
        const float v2 = c0*ex2(b0*e2) + c1*ex2(b1*e2) + c2*ex2(b2*e2) + c3*ex2(b3*e2);
        const float v3 = c0*ex2(b0*e3) + c1*ex2(b1*e3) + c2*ex2(b2*e3) + c3*ex2(b3*e3);

        // ---- sequential merge of the 4 sorted edges; flush interior runs ----
        cur = ii.x; acc = v0;
        if (ii.y == cur) acc += v1; else { atomicAdd(out + cur, acc); cur = ii.y; acc = v1; }
        if (ii.z == cur) acc += v2; else { atomicAdd(out + cur, acc); cur = ii.z; acc = v2; }
        if (ii.w == cur) acc += v3; else { atomicAdd(out + cur, acc); cur = ii.w; acc = v3; }
    } else if (base < E) {
        // ---- remainder path: scalar, direct atomics ----
        for (int e = base; e < E; e++) {
            const int   si = __ldg(idx_i + e);
            const int   sj = __ldg(idx_j + e);
            const float zpi = ex2(p * lg2((float)__ldg(Z + si)));
            const float zpj = ex2(p * lg2((float)__ldg(Z + sj)));
            const float ev  = __ldg(Dij + e) * (zpi + zpj);
            const float v   = c0*ex2(b0*ev) + c1*ex2(b1*ev) + c2*ex2(b2*ev) + c3*ex2(b3*ev);
            atomicAdd(out + si, v);
        }
        cur = -1; acc = 0.0f;
    }

    // ---- warp-level segmented inclusive scan over the pending tails ----
    // idx_i sorted -> equal tail ids are contiguous across lanes; the last
    // lane of each run issues one atomicAdd.
    const unsigned m = 0xFFFFFFFFu;
    const int lane = threadIdx.x & 31;
    #pragma unroll
    for (int o = 1; o < 32; o <<= 1) {
        const float vv = __shfl_up_sync(m, acc, o);
        const int   ss = __shfl_up_sync(m, cur, o);
        if (lane >= o && ss == cur) acc += vv;
    }
    const int nxt = __shfl_down_sync(m, cur, 1);
    if (cur >= 0 && (lane == 31 || nxt != cur)) {
        atomicAdd(out + cur, acc);
    }
}

// ---------------------------------------------------------------------------
extern "C" void kernel_launch(void* const* d_in, const int* in_sizes, int n_in,
                              void* d_out, int out_size)
{
    const int*   Z     = (const int*)  d_in[0];
    const float* Dij   = (const float*)d_in[1];
    const int*   idx_i = (const int*)  d_in[2];
    const int*   idx_j = (const int*)  d_in[3];
    const float* p_ptr = (const float*)d_in[4];
    const float* d_ptr = (const float*)d_in[5];
    const float* c_ptr = (const float*)d_in[6];
    const float* a_ptr = (const float*)d_in[7];
    float* out = (float*)d_out;

    const int E = in_sizes[1];

    // 1) zero the poisoned output (graph-capturable memset node)
    cudaMemsetAsync(out, 0, (size_t)out_size * sizeof(float));

    // 2) fused edge compute + sorted segment reduction
    const int threads = (E + EPT - 1) / EPT;
    const int blocks  = (threads + TPB - 1) / TPB;
    zbl_main_kernel<<<blocks, TPB>>>(Dij, idx_i, idx_j, Z,
                                     p_ptr, d_ptr, c_ptr, a_ptr, out, E);
}

// round 7
// speedup vs baseline: 1.6053x; 1.0058x over previous
#include <cuda_runtime.h>
#include <cuda_bf16.h>

// ZBL screened nuclear repulsion:
//   expv = Dij/d * (Zi^p + Zj^p)
//   vij  = sum_k c[k] * exp(-a[k]*expv)
//   out  = segment_sum(vij, idx_i)   (idx_i sorted)
//
// Inputs (metadata order):
//   0: Z     int32  [500000]
//   1: Dij   f32    [16000000]
//   2: idx_i int32  [16000000]   (sorted)
//   3: idx_j int32  [16000000]
//   4: p     f32    [1]
//   5: d     f32    [1]
//   6: c     f32    [4]
//   7: a     f32    [4]
// Output: f32 [500000]
//
// R7: R6 body (EPT=4, input-array Z gathers, MUFU z^p) wrapped in a
// fixed-trip grid-stride loop (ITERS=4) with NEXT-iteration streaming
// prefetch. Takes the ~600-cyc DRAM hop for Dij/idx off the critical
// dependence chain (R6 showed issue=48.5%: exposed latency, not pipe
// saturation). Front-batch depth per iteration stays ~11-14 LDGs — R4
// proved ~22 overflows the l1tex wavefront queue. #pragma unroll 1 keeps
// the compiler from fusing iterations back into one giant front batch.

#define EPT   4
#define TPB   256
#define ITERS 4

__device__ __forceinline__ float ex2(float x) {
    float y;
    asm("ex2.approx.f32 %0, %1;" : "=f"(y) : "f"(x));
    return y;
}
__device__ __forceinline__ float lg2(float x) {
    float y;
    asm("lg2.approx.f32 %0, %1;" : "=f"(y) : "f"(x));
    return y;
}

// ---------------------------------------------------------------------------
__global__ __launch_bounds__(TPB)
void zbl_main_kernel(const float4* __restrict__ Dij4,
                     const int4*   __restrict__ idx_i4,
                     const int4*   __restrict__ idx_j4,
                     const int*    __restrict__ Z,
                     const float*  __restrict__ p_ptr,
                     const float*  __restrict__ d_ptr,
                     const float*  __restrict__ c_ptr,
                     const float*  __restrict__ a_ptr,
                     float*        __restrict__ out,
                     int V)   // number of 4-edge vectors
{
    const float p    = __ldg(p_ptr);
    const float invd = 1.0f / __ldg(d_ptr);
    const float c0 = __ldg(c_ptr + 0), c1 = __ldg(c_ptr + 1);
    const float c2 = __ldg(c_ptr + 2), c3 = __ldg(c_ptr + 3);
    // b_k = -a_k * log2(e) / d : folds exp->ex2 base change and 1/d
    const float NL2E = -1.4426950408889634f * invd;
    const float b0 = __ldg(a_ptr + 0) * NL2E, b1 = __ldg(a_ptr + 1) * NL2E;
    const float b2 = __ldg(a_ptr + 2) * NL2E, b3 = __ldg(a_ptr + 3) * NL2E;

    const int stride = gridDim.x * blockDim.x;
    int v = blockIdx.x * blockDim.x + threadIdx.x;

    const unsigned m = 0xFFFFFFFFu;
    const int lane = threadIdx.x & 31;

    // ---- prologue: prefetch iteration 0's streaming data ----
    bool   valid = (v < V);
    float4 dd = make_float4(0.f, 0.f, 0.f, 0.f);
    int4   ii = make_int4(0, 0, 0, 0);
    int4   jj = make_int4(0, 0, 0, 0);
    if (valid) {
        dd = __ldg(Dij4   + v);
        ii = __ldg(idx_i4 + v);
        jj = __ldg(idx_j4 + v);
    }

    #pragma unroll 1
    for (int k = 0; k < ITERS; k++) {
        // ---- prefetch next iteration's streaming vectors (off critical path) ----
        const int  vn     = v + stride;
        const bool nvalid = (k + 1 < ITERS) && (vn < V);
        float4 dd_n = make_float4(0.f, 0.f, 0.f, 0.f);
        int4   ii_n = make_int4(0, 0, 0, 0);
        int4   jj_n = make_int4(0, 0, 0, 0);
        if (nvalid) {
            dd_n = __ldg(Dij4   + vn);
            ii_n = __ldg(idx_i4 + vn);
            jj_n = __ldg(idx_j4 + vn);
        }

        int   cur = -1;     // pending segment id (tail)
        float acc = 0.0f;   // pending segment sum

        if (valid) {
            // ---- 8 independent scalar gathers from the input Z array ----
            const int zi0 = __ldg(Z + ii.x), zi1 = __ldg(Z + ii.y);
            const int zi2 = __ldg(Z + ii.z), zi3 = __ldg(Z + ii.w);
            const int zj0 = __ldg(Z + jj.x), zj1 = __ldg(Z + jj.y);
            const int zj2 = __ldg(Z + jj.z), zj3 = __ldg(Z + jj.w);

            // ---- z^p via MUFU: ex2(p*lg2 z); z=0 -> -inf -> 0 = pow(0,p) ----
            const float fi0 = ex2(p * lg2((float)zi0));
            const float fi1 = ex2(p * lg2((float)zi1));
            const float fi2 = ex2(p * lg2((float)zi2));
            const float fi3 = ex2(p * lg2((float)zi3));
            const float fj0 = ex2(p * lg2((float)zj0));
            const float fj1 = ex2(p * lg2((float)zj1));
            const float fj2 = ex2(p * lg2((float)zj2));
            const float fj3 = ex2(p * lg2((float)zj3));

            const float e0 = dd.x * (fi0 + fj0);
            const float e1 = dd.y * (fi1 + fj1);
            const float e2 = dd.z * (fi2 + fj2);
            const float e3 = dd.w * (fi3 + fj3);

            const float v0 = c0*ex2(b0*e0) + c1*ex2(b1*e0) + c2*ex2(b2*e0) + c3*ex2(b3*e0);
            const float v1 = c0*ex2(b0*e1) + c1*ex2(b1*e1) + c2*ex2(b2*e1) + c3*ex2(b3*e1);
            const float v2 = c0*ex2(b0*e2) + c1*ex2(b1*e2) + c2*ex2(b2*e2) + c3*ex2(b3*e2);
            const float v3 = c0*ex2(b0*e3) + c1*ex2(b1*e3) + c2*ex2(b2*e3) + c3*ex2(b3*e3);

            // ---- sequential merge of the 4 sorted edges; flush interior runs ----
            cur = ii.x; acc = v0;
            if (ii.y == cur) acc += v1; else { atomicAdd(out + cur, acc); cur = ii.y; acc = v1; }
            if (ii.z == cur) acc += v2; else { atomicAdd(out + cur, acc); cur = ii.z; acc = v2; }
            if (ii.w == cur) acc += v3; else { atomicAdd(out + cur, acc); cur = ii.w; acc = v3; }
        }

        // ---- warp-segmented inclusive scan over the pending tails ----
        // Edges sorted by idx_i; lanes hold consecutive edge groups, so equal
        // tail ids are contiguous. Invalid lanes carry cur=-1 (top lanes only)
        // and are excluded by the cur>=0 guard.
        #pragma unroll
        for (int o = 1; o < 32; o <<= 1) {
            const float vv = __shfl_up_sync(m, acc, o);
            const int   ss = __shfl_up_sync(m, cur, o);
            if (lane >= o && ss == cur) acc += vv;
        }
        const int nxt = __shfl_down_sync(m, cur, 1);
        if (cur >= 0 && (lane == 31 || nxt != cur)) {
            atomicAdd(out + cur, acc);
        }

        // ---- rotate pipeline ----
        v = vn; valid = nvalid;
        dd = dd_n; ii = ii_n; jj = jj_n;
    }
}

// ---------------------------------------------------------------------------
// Tail kernel: handles E % 4 leftover edges (0 for this shape, but correct
// in general). Single tiny block.
__global__ void zbl_tail_kernel(const float* __restrict__ Dij,
                                const int*   __restrict__ idx_i,
                                const int*   __restrict__ idx_j,
                                const int*   __restrict__ Z,
                                const float* __restrict__ p_ptr,
                                const float* __restrict__ d_ptr,
                                const float* __restrict__ c_ptr,
                                const float* __restrict__ a_ptr,
                                float*       __restrict__ out,
                                int start, int E)
{
    const float p    = __ldg(p_ptr);
    const float invd = 1.0f / __ldg(d_ptr);
    const float NL2E = -1.4426950408889634f * invd;
    const int e = start + blockIdx.x * blockDim.x + threadIdx.x;
    if (e < E) {
        const int   si = __ldg(idx_i + e);
        const int   sj = __ldg(idx_j + e);
        const float zpi = ex2(p * lg2((float)__ldg(Z + si)));
        const float zpj = ex2(p * lg2((float)__ldg(Z + sj)));
        const float ev  = __ldg(Dij + e) * (zpi + zpj);
        float vsum = 0.0f;
        #pragma unroll
        for (int k = 0; k < 4; k++)
            vsum += __ldg(c_ptr + k) * ex2(__ldg(a_ptr + k) * NL2E * ev);
        atomicAdd(out + si, vsum);
    }
}

// ---------------------------------------------------------------------------
extern "C" void kernel_launch(void* const* d_in, const int* in_sizes, int n_in,
                              void* d_out, int out_size)
{
    const int*   Z     = (const int*)  d_in[0];
    const float* Dij   = (const float*)d_in[1];
    const int*   idx_i = (const int*)  d_in[2];
    const int*   idx_j = (const int*)  d_in[3];
    const float* p_ptr = (const float*)d_in[4];
    const float* d_ptr = (const float*)d_in[5];
    const float* c_ptr = (const float*)d_in[6];
    const float* a_ptr = (const float*)d_in[7];
    float* out = (float*)d_out;

    const int E = in_sizes[1];
    const int V = E / 4;            // full 4-edge vectors
    const int tail_start = V * 4;

    // 1) zero the poisoned output (graph-capturable memset node)
    cudaMemsetAsync(out, 0, (size_t)out_size * sizeof(float));

    // 2) pipelined main kernel: each thread handles ITERS vectors grid-stride
    {
        const long long threads_needed = ((long long)V + ITERS - 1) / ITERS;
        const int blocks = (int)((threads_needed + TPB - 1) / TPB);
        zbl_main_kernel<<<blocks, TPB>>>(
            reinterpret_cast<const float4*>(Dij),
            reinterpret_cast<const int4*>(idx_i),
            reinterpret_cast<const int4*>(idx_j),
            Z, p_ptr, d_ptr, c_ptr, a_ptr, out, V);
    }

    // 3) leftover edges (E % 4), if any
    if (tail_start < E) {
        const int n = E - tail_start;
        zbl_tail_kernel<<<(n + 63) / 64, 64>>>(Dij, idx_i, idx_j, Z,
                                               p_ptr, d_ptr, c_ptr, a_ptr,
                                               out, tail_start, E);
    }
}

// round 8
// speedup vs baseline: 1.6601x; 1.0341x over previous
#include <cuda_runtime.h>
#include <cuda_bf16.h>

// ZBL screened nuclear repulsion:
//   expv = Dij/d * (Zi^p + Zj^p)
//   vij  = sum_k c[k] * exp(-a[k]*expv)
//   out  = segment_sum(vij, idx_i)   (idx_i sorted)
//
// R8: R7 pipeline, slimmed. Only the idx vectors (the gather-chain roots)
// are prefetched across iterations; Dij is loaded in-body where its latency
// self-hides against the gathers. Cuts ~8 regs of double-buffer state that
// cost R7 31 points of occupancy (86% -> 55%) for only +3% issue.

#define EPT   4
#define TPB   256
#define ITERS 4

__device__ __forceinline__ float ex2(float x) {
    float y;
    asm("ex2.approx.f32 %0, %1;" : "=f"(y) : "f"(x));
    return y;
}
__device__ __forceinline__ float lg2(float x) {
    float y;
    asm("lg2.approx.f32 %0, %1;" : "=f"(y) : "f"(x));
    return y;
}

// ---------------------------------------------------------------------------
__global__ __launch_bounds__(TPB)
void zbl_main_kernel(const float4* __restrict__ Dij4,
                     const int4*   __restrict__ idx_i4,
                     const int4*   __restrict__ idx_j4,
                     const int*    __restrict__ Z,
                     const float*  __restrict__ p_ptr,
                     const float*  __restrict__ d_ptr,
                     const float*  __restrict__ c_ptr,
                     const float*  __restrict__ a_ptr,
                     float*        __restrict__ out,
                     int V)   // number of 4-edge vectors
{
    const float p    = __ldg(p_ptr);
    const float invd = 1.0f / __ldg(d_ptr);
    const float c0 = __ldg(c_ptr + 0), c1 = __ldg(c_ptr + 1);
    const float c2 = __ldg(c_ptr + 2), c3 = __ldg(c_ptr + 3);
    // b_k = -a_k * log2(e) / d : folds exp->ex2 base change and 1/d
    const float NL2E = -1.4426950408889634f * invd;
    const float b0 = __ldg(a_ptr + 0) * NL2E, b1 = __ldg(a_ptr + 1) * NL2E;
    const float b2 = __ldg(a_ptr + 2) * NL2E, b3 = __ldg(a_ptr + 3) * NL2E;

    const int stride = gridDim.x * blockDim.x;
    int v = blockIdx.x * blockDim.x + threadIdx.x;

    const unsigned m = 0xFFFFFFFFu;
    const int lane = threadIdx.x & 31;

    // ---- prologue: prefetch iteration 0's index vectors (gather roots) ----
    bool valid = (v < V);
    int4 ii = make_int4(0, 0, 0, 0);
    int4 jj = make_int4(0, 0, 0, 0);
    if (valid) {
        ii = __ldg(idx_i4 + v);
        jj = __ldg(idx_j4 + v);
    }

    #pragma unroll 1
    for (int k = 0; k < ITERS; k++) {
        int   cur = -1;     // pending segment id (tail)
        float acc = 0.0f;   // pending segment sum

        // next iteration's index prefetch (issued before this iteration's
        // dependent work so the DRAM hop overlaps the gather+math+scan)
        const int  vn     = v + stride;
        const bool nvalid = (k + 1 < ITERS) && (vn < V);
        int4 ii_n = make_int4(0, 0, 0, 0);
        int4 jj_n = make_int4(0, 0, 0, 0);
        if (nvalid) {
            ii_n = __ldg(idx_i4 + vn);
            jj_n = __ldg(idx_j4 + vn);
        }

        if (valid) {
            // ---- Dij load: independent of the gather chain, self-hiding ----
            const float4 dd = __ldg(Dij4 + v);

            // ---- 8 independent scalar gathers from the input Z array ----
            const int zi0 = __ldg(Z + ii.x), zi1 = __ldg(Z + ii.y);
            const int zi2 = __ldg(Z + ii.z), zi3 = __ldg(Z + ii.w);
            const int zj0 = __ldg(Z + jj.x), zj1 = __ldg(Z + jj.y);
            const int zj2 = __ldg(Z + jj.z), zj3 = __ldg(Z + jj.w);

            // ---- z^p via MUFU: ex2(p*lg2 z); z=0 -> -inf -> 0 = pow(0,p) ----
            const float fi0 = ex2(p * lg2((float)zi0));
            const float fi1 = ex2(p * lg2((float)zi1));
            const float fi2 = ex2(p * lg2((float)zi2));
            const float fi3 = ex2(p * lg2((float)zi3));
            const float fj0 = ex2(p * lg2((float)zj0));
            const float fj1 = ex2(p * lg2((float)zj1));
            const float fj2 = ex2(p * lg2((float)zj2));
            const float fj3 = ex2(p * lg2((float)zj3));

            const float e0 = dd.x * (fi0 + fj0);
            const float e1 = dd.y * (fi1 + fj1);
            const float e2 = dd.z * (fi2 + fj2);
            const float e3 = dd.w * (fi3 + fj3);

            const float v0 = c0*ex2(b0*e0) + c1*ex2(b1*e0) + c2*ex2(b2*e0) + c3*ex2(b3*e0);
            const float v1 = c0*ex2(b0*e1) + c1*ex2(b1*e1) + c2*ex2(b2*e1) + c3*ex2(b3*e1);
            const float v2 = c0*ex2(b0*e2) + c1*ex2(b1*e2) + c2*ex2(b2*e2) + c3*ex2(b3*e2);
            const float v3 = c0*ex2(b0*e3) + c1*ex2(b1*e3) + c2*ex2(b2*e3) + c3*ex2(b3*e3);

            // ---- sequential merge of the 4 sorted edges; flush interior runs ----
            cur = ii.x; acc = v0;
            if (ii.y == cur) acc += v1; else { atomicAdd(out + cur, acc); cur = ii.y; acc = v1; }
            if (ii.z == cur) acc += v2; else { atomicAdd(out + cur, acc); cur = ii.z; acc = v2; }
            if (ii.w == cur) acc += v3; else { atomicAdd(out + cur, acc); cur = ii.w; acc = v3; }
        }

        // ---- warp-segmented inclusive scan over the pending tails ----
        // Edges sorted by idx_i; equal tail ids are contiguous across lanes.
        // Invalid lanes carry cur=-1 and are excluded by the cur>=0 guard.
        #pragma unroll
        for (int o = 1; o < 32; o <<= 1) {
            const float vv = __shfl_up_sync(m, acc, o);
            const int   ss = __shfl_up_sync(m, cur, o);
            if (lane >= o && ss == cur) acc += vv;
        }
        const int nxt = __shfl_down_sync(m, cur, 1);
        if (cur >= 0 && (lane == 31 || nxt != cur)) {
            atomicAdd(out + cur, acc);
        }

        // ---- rotate pipeline ----
        v = vn; valid = nvalid;
        ii = ii_n; jj = jj_n;
    }
}

// ---------------------------------------------------------------------------
// Tail kernel: handles E % 4 leftover edges (0 for this shape, but correct
// in general).
__global__ void zbl_tail_kernel(const float* __restrict__ Dij,
                                const int*   __restrict__ idx_i,
                                const int*   __restrict__ idx_j,
                                const int*   __restrict__ Z,
                                const float* __restrict__ p_ptr,
                                const float* __restrict__ d_ptr,
                                const float* __restrict__ c_ptr,
                                const float* __restrict__ a_ptr,
                                float*       __restrict__ out,
                                int start, int E)
{
    const float p    = __ldg(p_ptr);
    const float invd = 1.0f / __ldg(d_ptr);
    const float NL2E = -1.4426950408889634f * invd;
    const int e = start + blockIdx.x * blockDim.x + threadIdx.x;
    if (e < E) {
        const int   si = __ldg(idx_i + e);
        const int   sj = __ldg(idx_j + e);
        const float zpi = ex2(p * lg2((float)__ldg(Z + si)));
        const float zpj = ex2(p * lg2((float)__ldg(Z + sj)));
        const float ev  = __ldg(Dij + e) * (zpi + zpj);
        float vsum = 0.0f;
        #pragma unroll
        for (int k = 0; k < 4; k++)
            vsum += __ldg(c_ptr + k) * ex2(__ldg(a_ptr + k) * NL2E * ev);
        atomicAdd(out + si, vsum);
    }
}

// ---------------------------------------------------------------------------
extern "C" void kernel_launch(void* const* d_in, const int* in_sizes, int n_in,
                              void* d_out, int out_size)
{
    const int*   Z     = (const int*)  d_in[0];
    const float* Dij   = (const float*)d_in[1];
    const int*   idx_i = (const int*)  d_in[2];
    const int*   idx_j = (const int*)  d_in[3];
    const float* p_ptr = (const float*)d_in[4];
    const float* d_ptr = (const float*)d_in[5];
    const float* c_ptr = (const float*)d_in[6];
    const float* a_ptr = (const float*)d_in[7];
    float* out = (float*)d_out;

    const int E = in_sizes[1];
    const int V = E / 4;            // full 4-edge vectors
    const int tail_start = V * 4;

    // 1) zero the poisoned output (graph-capturable memset node)
    cudaMemsetAsync(out, 0, (size_t)out_size * sizeof(float));

    // 2) pipelined main kernel: each thread handles ITERS vectors grid-stride
    {
        const long long threads_needed = ((long long)V + ITERS - 1) / ITERS;
        const int blocks = (int)((threads_needed + TPB - 1) / TPB);
        zbl_main_kernel<<<blocks, TPB>>>(
            reinterpret_cast<const float4*>(Dij),
            reinterpret_cast<const int4*>(idx_i),
            reinterpret_cast<const int4*>(idx_j),
            Z, p_ptr, d_ptr, c_ptr, a_ptr, out, V);
    }

    // 3) leftover edges (E % 4), if any
    if (tail_start < E) {
        const int n = E - tail_start;
        zbl_tail_kernel<<<(n + 63) / 64, 64>>>(Dij, idx_i, idx_j, Z,
                                               p_ptr, d_ptr, c_ptr, a_ptr,
                                               out, tail_start, E);
    }
}